// round 4
// baseline (speedup 1.0000x reference)
#include <cuda_runtime.h>
#include <math.h>

#define NB 32
#define CI 8
#define CO 8
#define KR 4
#define DI 16
#define DOUT 16
#define SS 32
#define NPIX 1024   // 32*32
#define PLANE (DOUT*NPIX)   // 16384

#define CAPS_RS 35           // padded row stride (floats), odd -> conflict-free
#define CAPS_CS (34*CAPS_RS) // channel stride = 1190
#define VOTE_RS 33           // votes row stride
#define VOTE_CS (32*VOTE_RS) // votes channel stride = 1056
#define VOTE_PS (8*VOTE_CS)  // votes plane stride = 8448

typedef unsigned long long u64;

// ---------------- scratch (static device globals; no allocation) -------------
__device__ float g_pooled[NB*CO*2*PLANE];   // [b][o][2][d][u][v]  33.5 MB
__device__ float g_preroute[NB*CO*PLANE];   // [b][o][d][u][v]     16.8 MB
__device__ float g_gate[NB*CO*PLANE];       // [b][o][d][u][v]     16.8 MB
__device__ double g_part[2*CO*NB];          // BN partial sums
__device__ float g_bnab[2*CO];              // per-o BN affine (scale, offset)

// packed fp32x2 FMA on u64 carriers: d = a*b + d
__device__ __forceinline__ void ffma2(u64& d, const u64 a, const u64 b) {
    asm("fma.rn.f32x2 %0, %1, %2, %0;" : "+l"(d) : "l"(a), "l"(b));
}
__device__ __forceinline__ u64 pack2(float x, float y) {
    u64 r; asm("mov.b64 %0, {%1,%2};" : "=l"(r) : "f"(x), "f"(y)); return r;
}
__device__ __forceinline__ float2 unpack2(u64 v) {
    float2 r; asm("mov.b64 {%0,%1}, %2;" : "=f"(r.x), "=f"(r.y) : "l"(v)); return r;
}

// ---------------------------------------------------------------------------
// K1: fused conv_trans (d-paired f32x2, conflict-free smem) + einsum + pool +
// routing-pre.  grid (o=8, b=32), 512 threads, ~214 KB dynamic smem
// ---------------------------------------------------------------------------
extern "C" __global__ void __launch_bounds__(512, 1)
k1_conv_route(const float* __restrict__ caps, const float* __restrict__ Wt,
              const float* __restrict__ bt, const float* __restrict__ Wv,
              const float* __restrict__ bv)
{
    extern __shared__ float sm[];
    float* s_caps  = sm;                          // 16*34*35 = 19040 floats
    u64*   s_wpd   = (u64*)(s_caps + 19040);      // 9216 u64 (d-paired conv w)
    float* s_votes = (float*)(s_wpd + 9216);      // 2*8*32*33 = 16896 floats
    u64*   s_wp    = (u64*)(s_votes + 16896);     // 128 u64 (k-paired Wv)
    u64*   s_bvp   = s_wp + 128;                  // 16 u64
    u64*   s_biasp = s_bvp + 16;                  // 64 u64 (d-paired bias)

    const int o = blockIdx.x, b = blockIdx.y;
    const int tid = threadIdx.x;

    // padded input image for this batch (rows 0..33 = orig -1..32, cols same)
    for (int idx = tid; idx < DI*34*34; idx += 512) {
        int ch = idx / 1156, rem = idx % 1156;
        int pr = rem / 34, pc = rem % 34;
        float v = 0.f;
        if (pr >= 1 && pr <= SS && pc >= 1 && pc <= SS)
            v = caps[((b*DI + ch)*SS + (pr-1))*SS + (pc-1)];
        s_caps[ch*CAPS_CS + pr*CAPS_RS + pc] = v;
    }
    // conv weights pre-packed over d-pairs
    for (int idx = tid; idx < 9216; idx += 512) {
        int tap = idx % 9, cin = (idx/9) & 15, dp = (idx/144) & 7, c = idx/1152;
        const float* wb = Wt + ((c*CO + o)*DOUT)*144 + cin*9 + tap;
        s_wpd[idx] = pack2(wb[(2*dp)*144], wb[(2*dp+1)*144]);
    }
    if (tid < 64) {
        int c = tid >> 3, dp = tid & 7;
        s_biasp[tid] = pack2(bt[(c*CO + o)*DOUT + 2*dp], bt[(c*CO + o)*DOUT + 2*dp+1]);
    }
    // value-conv weights k-paired
    for (int idx = tid; idx < 128; idx += 512) {
        int c2 = idx >> 4, ci = (idx >> 1) & 7, h = idx & 1;
        s_wp[idx] = pack2(Wv[o*256 + ((2*h)*8 + c2)*8 + ci],
                          Wv[o*256 + ((2*h+1)*8 + c2)*8 + ci]);
    }
    if (tid < 16) {
        int c2 = tid >> 1, h = tid & 1;
        s_bvp[tid] = pack2(bv[o*32 + (2*h)*8 + c2], bv[o*32 + (2*h+1)*8 + c2]);
    }
    __syncthreads();

    // lane = output row (conflict-free smem); warp selects (c, col-half)
    const int w    = tid >> 5;        // warp 0..15
    const int c    = w >> 1;          // C_in channel of votes
    const int cb   = (w & 1) << 4;    // column base 0 or 16
    const int r    = tid & 31;        // output row = lane
    const int obase = b*CO + o;

    for (int dp = 0; dp < 8; dp++) {
        // ---- Phase A: votes for d-pair (2dp, 2dp+1)
        u64 acc[16];
        {
            u64 bp = s_biasp[c*8 + dp];
            #pragma unroll
            for (int j = 0; j < 16; j++) acc[j] = bp;
        }
        const u64* wbase = s_wpd + (c*8 + dp)*144;
        #pragma unroll 1
        for (int cin = 0; cin < DI; cin++) {
            const u64* wc = wbase + cin*9;
            const float* xb = s_caps + cin*CAPS_CS + r*CAPS_RS + cb;
            #pragma unroll
            for (int dy = 0; dy < 3; dy++) {
                const float* xr = xb + dy*CAPS_RS;
                u64 xp[18];
                #pragma unroll
                for (int i = 0; i < 18; i++) { float v = xr[i]; xp[i] = pack2(v, v); }
                u64 w0 = wc[dy*3+0], w1 = wc[dy*3+1], w2 = wc[dy*3+2];
                #pragma unroll
                for (int j = 0; j < 16; j++) {
                    ffma2(acc[j], xp[j],   w0);
                    ffma2(acc[j], xp[j+1], w1);
                    ffma2(acc[j], xp[j+2], w2);
                }
            }
        }
        {
            float* v0 = s_votes + c*VOTE_CS + r*VOTE_RS + cb;
            #pragma unroll
            for (int j = 0; j < 16; j++) {
                float2 v = unpack2(acc[j]);
                v0[j] = v.x;
                v0[VOTE_PS + j] = v.y;
            }
        }
        __syncthreads();

        // ---- Phase B: per-pixel 32x8 matvec, c2-outer with weights in regs,
        //      2 pixels per plane per thread
        #pragma unroll 1
        for (int pl = 0; pl < 2; pl++) {
            int d = dp*2 + pl;
            // load votes for 2 pixels: p0 = tid, p1 = tid+512
            u64 vd[2][8];
            #pragma unroll
            for (int pp = 0; pp < 2; pp++) {
                int p = tid + pp*512;
                int prow = p >> 5, pcol = p & 31;
                const float* vb = s_votes + pl*VOTE_PS + prow*VOTE_RS + pcol;
                #pragma unroll
                for (int ci = 0; ci < 8; ci++) {
                    float v = vb[ci*VOTE_CS];
                    vd[pp][ci] = pack2(v, v);
                }
            }
            float vmax[2] = {-3.0e38f, -3.0e38f};
            float vsum[2] = {0.f, 0.f};
            float num[2]  = {0.f, 0.f};
            float den[2]  = {0.f, 0.f};
            #pragma unroll
            for (int c2 = 0; c2 < 8; c2++) {
                u64 wreg[16];
                #pragma unroll
                for (int i = 0; i < 16; i++) wreg[i] = s_wp[c2*16 + i];
                u64 b0 = s_bvp[c2*2 + 0];
                u64 b1 = s_bvp[c2*2 + 1];
                #pragma unroll
                for (int pp = 0; pp < 2; pp++) {
                    u64 a0 = b0, a1 = b1;
                    #pragma unroll
                    for (int ci = 0; ci < 8; ci++) {
                        ffma2(a0, vd[pp][ci], wreg[ci*2 + 0]);
                        ffma2(a1, vd[pp][ci], wreg[ci*2 + 1]);
                    }
                    float2 p0 = unpack2(a0), p1 = unpack2(a1);
                    float v0 = p0.x, v1 = p0.y, v2 = p1.x, v3 = p1.y;
                    vmax[pp] = fmaxf(vmax[pp], fmaxf(fmaxf(v0, v1), fmaxf(v2, v3)));
                    float sum4 = (v0 + v1) + (v2 + v3);
                    vsum[pp] += sum4;
                    float mu = 0.25f*sum4;
                    float d0 = v0-mu, d1 = v1-mu, d2 = v2-mu, d3 = v3-mu;
                    float var = 0.25f*((d0*d0 + d1*d1) + (d2*d2 + d3*d3));
                    float rr = rsqrtf(var);           // = 1/std
                    num[pp] += rr*mu;
                    den[pp] += rr;
                }
            }
            #pragma unroll
            for (int pp = 0; pp < 2; pp++) {
                int p = tid + pp*512;
                g_pooled[(obase*2 + 0)*PLANE + d*NPIX + p] = vmax[pp];
                g_pooled[(obase*2 + 1)*PLANE + d*NPIX + p] = vsum[pp]*(1.f/32.f);
                g_preroute[obase*PLANE + d*NPIX + p] = num[pp]/den[pp];
            }
        }
        __syncthreads();
    }
}

// ---------------------------------------------------------------------------
// K2: spatial gate 3x3x3 conv (2ch -> 1, pad 1) + BN partial sums (fp64)
// ---------------------------------------------------------------------------
extern "C" __global__ void __launch_bounds__(512, 1)
k2_gate(const float* __restrict__ Ws)
{
    extern __shared__ float sp[];  // [2][18][34][34] zero-padded pooled
    __shared__ float s_ws[54];
    __shared__ double s_redA[16], s_redB[16];

    const int o = blockIdx.x, b = blockIdx.y;
    const int tid = threadIdx.x;
    const int obase = b*CO + o;

    if (tid < 54) s_ws[tid] = Ws[tid];
    for (int idx = tid; idx < 2*18*1156; idx += 512) {
        int ch = idx / 20808, rem = idx % 20808;
        int dd = rem / 1156, r2 = (rem % 1156)/34, cc = rem % 34;
        float v = 0.f;
        if (dd >= 1 && dd <= 16 && r2 >= 1 && r2 <= 32 && cc >= 1 && cc <= 32)
            v = g_pooled[(obase*2 + ch)*PLANE + (dd-1)*NPIX + (r2-1)*32 + (cc-1)];
        sp[idx] = v;
    }
    __syncthreads();

    const int d = tid >> 5, u = tid & 31;   // one output row per thread
    float acc[32];
    #pragma unroll
    for (int v = 0; v < 32; v++) acc[v] = 0.f;
    #pragma unroll 1
    for (int ch = 0; ch < 2; ch++) {
        #pragma unroll
        for (int kd = 0; kd < 3; kd++) {
            #pragma unroll
            for (int kh = 0; kh < 3; kh++) {
                const float* xr = sp + ch*20808 + (d+kd)*1156 + (u+kh)*34;
                float xx[34];
                #pragma unroll
                for (int j = 0; j < 34; j++) xx[j] = xr[j];
                const float* wp = s_ws + ch*27 + kd*9 + kh*3;
                float w0 = wp[0], w1 = wp[1], w2 = wp[2];
                #pragma unroll
                for (int v = 0; v < 32; v++)
                    acc[v] += w0*xx[v] + w1*xx[v+1] + w2*xx[v+2];
            }
        }
    }
    double s = 0.0, s2 = 0.0;
    float* gout = g_gate + obase*PLANE + tid*32;
    #pragma unroll
    for (int v = 0; v < 32; v++) {
        gout[v] = acc[v];
        double dv = (double)acc[v];
        s += dv; s2 += dv*dv;
    }
    #pragma unroll
    for (int off = 16; off > 0; off >>= 1) {
        s  += __shfl_down_sync(0xffffffffu, s,  off);
        s2 += __shfl_down_sync(0xffffffffu, s2, off);
    }
    int w = tid >> 5;
    if ((tid & 31) == 0) { s_redA[w] = s; s_redB[w] = s2; }
    __syncthreads();
    if (tid < 32) {
        double a = (tid < 16) ? s_redA[tid] : 0.0;
        double bq = (tid < 16) ? s_redB[tid] : 0.0;
        #pragma unroll
        for (int off = 8; off > 0; off >>= 1) {
            a  += __shfl_down_sync(0xffffffffu, a,  off);
            bq += __shfl_down_sync(0xffffffffu, bq, off);
        }
        if (tid == 0) {
            g_part[o*NB + b] = a;
            g_part[CO*NB + o*NB + b] = bq;
        }
    }
}

// ---------------------------------------------------------------------------
extern "C" __global__ void k2b_bn(const float* __restrict__ bng,
                                  const float* __restrict__ bnb)
{
    int o = threadIdx.x;
    if (o < CO) {
        double s = 0.0, s2 = 0.0;
        for (int b = 0; b < NB; b++) {
            s  += g_part[o*NB + b];
            s2 += g_part[CO*NB + o*NB + b];
        }
        double n = (double)NB * PLANE;
        double mu = s / n;
        double var = s2 / n - mu*mu;
        float rstd = (float)(1.0 / sqrt(var + 1e-5));
        float a = bng[0] * rstd;
        g_bnab[o] = a;
        g_bnab[CO + o] = bnb[0] - (float)mu * a;
    }
}

// ---------------------------------------------------------------------------
// K3: caps_next = (1+sigmoid(BN(g)))*preroute, LayerNorm, transpose-write
// ---------------------------------------------------------------------------
extern "C" __global__ void __launch_bounds__(512)
k3_finalize(const float* __restrict__ lng, const float* __restrict__ lnb,
            float* __restrict__ out)
{
    __shared__ float s_red[16];
    const int o = blockIdx.x, b = blockIdx.y;
    const int tid = threadIdx.x;
    const int base = (b*CO + o)*PLANE;
    const float a = g_bnab[o], ofs = g_bnab[CO + o];

    float x[32];
    float s = 0.f;
    #pragma unroll
    for (int i = 0; i < 32; i++) {
        int idx = tid + i*512;
        float g = g_gate[base + idx];
        float z = g*a + ofs;
        float sg = 1.f / (1.f + expf(-z));
        float val = g_preroute[base + idx] * (1.f + sg);
        x[i] = val; s += val;
    }
    #pragma unroll
    for (int off = 16; off > 0; off >>= 1) s += __shfl_down_sync(0xffffffffu, s, off);
    int w = tid >> 5;
    if ((tid & 31) == 0) s_red[w] = s;
    __syncthreads();
    if (tid < 32) {
        float t = (tid < 16) ? s_red[tid] : 0.f;
        #pragma unroll
        for (int off = 8; off > 0; off >>= 1) t += __shfl_down_sync(0xffffffffu, t, off);
        if (tid == 0) s_red[0] = t;
    }
    __syncthreads();
    float m = s_red[0] * (1.f/16384.f);
    __syncthreads();

    float v = 0.f;
    #pragma unroll
    for (int i = 0; i < 32; i++) { float dd = x[i] - m; v += dd*dd; }
    #pragma unroll
    for (int off = 16; off > 0; off >>= 1) v += __shfl_down_sync(0xffffffffu, v, off);
    if ((tid & 31) == 0) s_red[w] = v;
    __syncthreads();
    if (tid < 32) {
        float t = (tid < 16) ? s_red[tid] : 0.f;
        #pragma unroll
        for (int off = 8; off > 0; off >>= 1) t += __shfl_down_sync(0xffffffffu, t, off);
        if (tid == 0) s_red[0] = t;
    }
    __syncthreads();
    float rstd = rsqrtf(s_red[0]*(1.f/16384.f) + 1e-5f);

    float* op = out + (o*NB + b)*PLANE;
    #pragma unroll
    for (int i = 0; i < 32; i++) {
        int idx = tid + i*512;
        op[idx] = (x[i] - m)*rstd*lng[idx] + lnb[idx];
    }
}

// ---------------------------------------------------------------------------
extern "C" void kernel_launch(void* const* d_in, const int* in_sizes, int n_in,
                              void* d_out, int out_size)
{
    const float* caps = (const float*)d_in[0];
    const float* Wt   = (const float*)d_in[1];
    const float* bt   = (const float*)d_in[2];
    const float* Wv   = (const float*)d_in[3];
    const float* bv   = (const float*)d_in[4];
    const float* Ws   = (const float*)d_in[5];
    const float* bng  = (const float*)d_in[6];
    const float* bnb  = (const float*)d_in[7];
    const float* lng  = (const float*)d_in[8];
    const float* lnb  = (const float*)d_in[9];
    float* out = (float*)d_out;

    // 19040 + 18432 + 16896 + 256 + 32 + 128 floats = 54784 f = 219136 B
    const int smem1 = 54784 * 4;
    const int smem2 = (2*18*1156) * 4;   // 166464
    cudaFuncSetAttribute(k1_conv_route, cudaFuncAttributeMaxDynamicSharedMemorySize, smem1);
    cudaFuncSetAttribute(k2_gate,       cudaFuncAttributeMaxDynamicSharedMemorySize, smem2);

    dim3 grid(CO, NB);
    k1_conv_route<<<grid, 512, smem1>>>(caps, Wt, bt, Wv, bv);
    k2_gate<<<grid, 512, smem2>>>(Ws);
    k2b_bn<<<1, 32>>>(bng, bnb);
    k3_finalize<<<grid, 512>>>(lng, lnb, out);
}

// round 6
// speedup vs baseline: 1.1141x; 1.1141x over previous
#include <cuda_runtime.h>
#include <math.h>

#define NB 32
#define CI 8
#define CO 8
#define KR 4
#define DI 16
#define DOUT 16
#define SS 32
#define NPIX 1024
#define PLANE (DOUT*NPIX)   // 16384

#define KTOT 432            // 3 segments x 144
#define KC   48             // K per chunk (6 mma k-steps)
#define NCHUNK 9
#define A_ST 52             // smem row stride (floats): 20g+t mod 32 all-distinct
#define B_ST 52
#define V_ST 129

typedef unsigned long long u64;
typedef unsigned int u32;

// ---------------- scratch (static device globals; no allocation) -------------
__device__ float g_pooled[NB*CO*2*PLANE];    // 33.5 MB
__device__ float g_preroute[NB*CO*PLANE];    // 16.8 MB
__device__ float g_gate[NB*CO*PLANE];        // 16.8 MB
__device__ double g_part[2*CO*NB];
__device__ float g_bnab[2*CO];
__device__ float g_X2[NB*NPIX*KTOT];         // [b][pix][Xh|Xh|Xl]  56.6 MB
__device__ float g_W2[CO*128*KTOT];          // [o][m][Wh|Wl|Wh]

// ---------------- helpers ----------------------------------------------------
__device__ __forceinline__ void ffma2(u64& d, const u64 a, const u64 b) {
    asm("fma.rn.f32x2 %0, %1, %2, %0;" : "+l"(d) : "l"(a), "l"(b));
}
__device__ __forceinline__ u64 pack2(float x, float y) {
    u64 r; asm("mov.b64 %0, {%1,%2};" : "=l"(r) : "f"(x), "f"(y)); return r;
}
__device__ __forceinline__ float2 unpack2(u64 v) {
    float2 r; asm("mov.b64 {%0,%1}, %2;" : "=f"(r.x), "=f"(r.y) : "l"(v)); return r;
}
// warp-level tf32 tensor-core mma (sm_80+ PTX, works at compute_103 target)
__device__ __forceinline__ void mma_tf32(float* d, const u32* a, const u32* b) {
    asm volatile(
        "mma.sync.aligned.m16n8k8.row.col.f32.tf32.tf32.f32 "
        "{%0,%1,%2,%3}, {%4,%5,%6,%7}, {%8,%9}, {%0,%1,%2,%3};"
        : "+f"(d[0]), "+f"(d[1]), "+f"(d[2]), "+f"(d[3])
        : "r"(a[0]), "r"(a[1]), "r"(a[2]), "r"(a[3]), "r"(b[0]), "r"(b[1]));
}
__device__ __forceinline__ float tf32_hi(float v) {
    return __uint_as_float(__float_as_uint(v) & 0xFFFFE000u);  // 10 mantissa bits, exact
}

// ---------------------------------------------------------------------------
// K0: build split operands.  blocks 0..31: X for batch b; block 32: W.
// ---------------------------------------------------------------------------
extern "C" __global__ void __launch_bounds__(1024)
k0_prep(const float* __restrict__ caps, const float* __restrict__ Wt)
{
    extern __shared__ float sp[];   // 16*34*34 = 18496
    const int tid = threadIdx.x;
    if (blockIdx.x < NB) {
        const int b = blockIdx.x;
        for (int idx = tid; idx < DI*1156; idx += 1024) {
            int ch = idx / 1156, rem = idx % 1156;
            int pr = rem / 34, pc = rem % 34;
            float v = 0.f;
            if (pr >= 1 && pr <= SS && pc >= 1 && pc <= SS)
                v = caps[((b*DI + ch)*SS + (pr-1))*SS + (pc-1)];
            sp[idx] = v;
        }
        __syncthreads();
        for (int idx = tid; idx < NPIX*144; idx += 1024) {
            int pix = idx / 144, s = idx % 144;
            int cin = s / 9, tap = s % 9;
            int dy = tap / 3, dx = tap % 3;
            int prow = pix >> 5, pcol = pix & 31;
            float v = sp[cin*1156 + (prow+dy)*34 + (pcol+dx)];
            float hi = tf32_hi(v);
            float* dst = g_X2 + (b*NPIX + pix)*KTOT + s;
            dst[0]   = hi;      // seg0: Xh
            dst[144] = hi;      // seg1: Xh
            dst[288] = v - hi;  // seg2: Xl
        }
    } else {
        for (int idx = tid; idx < CO*128*144; idx += 1024) {
            int s = idx % 144, m = (idx/144) & 127, o = idx/(144*128);
            int c = m >> 4, d = m & 15;
            float v = Wt[(((c*CO + o)*DOUT + d)*144) + s];
            float hi = tf32_hi(v);
            float* dst = g_W2 + (o*128 + m)*KTOT + s;
            dst[0]   = hi;      // seg0: Wh
            dst[144] = v - hi;  // seg1: Wl
            dst[288] = hi;      // seg2: Wh
        }
    }
}

// ---------------------------------------------------------------------------
// K1: mma.sync 3xTF32 conv-GEMM (M=128, N=1024, K=432) + einsum + pool +
// routing-pre.  grid (o=8, b=32), 512 threads, 134 KB dynamic smem.
// smem floats: [0,256) s_wp(u64x128) | [256,288) s_bvp(u64x16) | [288,416) bias
//   [512, 7168)  s_A 128x52      (aliased by s_votes)
//   [7168,20480) s_B 256x52      (aliased by s_votes)
//   [512, 33536) s_votes 256x129 (after GEMM of each ntile)
// ---------------------------------------------------------------------------
extern "C" __global__ void __launch_bounds__(512, 1)
k1_conv_route(const float* __restrict__ bt, const float* __restrict__ Wv,
              const float* __restrict__ bv)
{
    extern __shared__ float sm[];
    u64*   s_wp    = (u64*)sm;
    u64*   s_bvp   = (u64*)(sm + 256);
    float* s_bias  = sm + 288;
    float* s_A     = sm + 512;
    float* s_B     = sm + 7168;
    float* s_votes = sm + 512;

    const int o = blockIdx.x, b = blockIdx.y;
    const int tid  = threadIdx.x;
    const int w    = tid >> 5, lane = tid & 31;
    const int wm   = w & 3,  wn = w >> 2;       // warp tile: rows wm*32, cols wn*64
    const int g    = lane >> 2, t = lane & 3;
    const int obase = b*CO + o;

    // tables
    for (int idx = tid; idx < 128; idx += 512) {
        int c2 = idx >> 4, ci = (idx >> 1) & 7, h = idx & 1;
        s_wp[idx] = pack2(Wv[o*256 + ((2*h)*8 + c2)*8 + ci],
                          Wv[o*256 + ((2*h+1)*8 + c2)*8 + ci]);
    }
    if (tid < 16) {
        int c2 = tid >> 1, h = tid & 1;
        s_bvp[tid] = pack2(bv[o*32 + (2*h)*8 + c2], bv[o*32 + (2*h+1)*8 + c2]);
    }
    if (tid < 128)
        s_bias[tid] = bt[(((tid >> 4)*CO + o)*DOUT) + (tid & 15)];
    __syncthreads();

    for (int ntile = 0; ntile < 4; ntile++) {
        const int tb = ntile*256;
        float acc[2][8][4];
        #pragma unroll
        for (int mi = 0; mi < 2; mi++)
            #pragma unroll
            for (int nj = 0; nj < 8; nj++)
                #pragma unroll
                for (int e = 0; e < 4; e++) acc[mi][nj][e] = 0.f;

        for (int kc = 0; kc < NCHUNK; kc++) {
            const int koff = kc*KC;
            // stage A chunk: 128 x 48 floats (1536 float4)
            #pragma unroll
            for (int i = tid; i < 1536; i += 512) {
                int m = i / 12, j4 = i % 12;
                float4 v = *(const float4*)(g_W2 + (o*128 + m)*KTOT + koff + j4*4);
                *(float4*)(s_A + m*A_ST + j4*4) = v;
            }
            // stage B chunk: 256 x 48 floats (3072 float4)
            #pragma unroll
            for (int i = tid; i < 3072; i += 512) {
                int pr = i / 12, j4 = i % 12;
                float4 v = *(const float4*)(g_X2 + (b*NPIX + tb + pr)*KTOT + koff + j4*4);
                *(float4*)(s_B + pr*B_ST + j4*4) = v;
            }
            __syncthreads();
            // 6 k-steps of m16n8k8
            #pragma unroll
            for (int ks = 0; ks < 6; ks++) {
                const int kb = ks*8;
                u32 afr[2][4];
                #pragma unroll
                for (int mi = 0; mi < 2; mi++) {
                    const float* ar = s_A + (wm*32 + mi*16 + g)*A_ST + kb + t;
                    afr[mi][0] = __float_as_uint(ar[0]);
                    afr[mi][1] = __float_as_uint(ar[8*A_ST]);
                    afr[mi][2] = __float_as_uint(ar[4]);
                    afr[mi][3] = __float_as_uint(ar[8*A_ST + 4]);
                }
                u32 bfr[8][2];
                #pragma unroll
                for (int nj = 0; nj < 8; nj++) {
                    const float* br = s_B + (wn*64 + nj*8 + g)*B_ST + kb + t;
                    bfr[nj][0] = __float_as_uint(br[0]);
                    bfr[nj][1] = __float_as_uint(br[4]);
                }
                #pragma unroll
                for (int mi = 0; mi < 2; mi++)
                    #pragma unroll
                    for (int nj = 0; nj < 8; nj++)
                        mma_tf32(acc[mi][nj], afr[mi], bfr[nj]);
            }
            __syncthreads();
        }

        // ---- stage votes (+bias) into s_votes[pix][m] (aliases A/B; regs safe)
        #pragma unroll
        for (int mi = 0; mi < 2; mi++) {
            int m0 = wm*32 + mi*16 + g;
            float bias0 = s_bias[m0], bias1 = s_bias[m0 + 8];
            #pragma unroll
            for (int nj = 0; nj < 8; nj++) {
                int p0 = wn*64 + nj*8 + 2*t;
                s_votes[p0*V_ST + m0]           = acc[mi][nj][0] + bias0;
                s_votes[(p0+1)*V_ST + m0]       = acc[mi][nj][1] + bias0;
                s_votes[p0*V_ST + m0 + 8]       = acc[mi][nj][2] + bias1;
                s_votes[(p0+1)*V_ST + m0 + 8]   = acc[mi][nj][3] + bias1;
            }
        }
        __syncthreads();

        // ---- Phase B: per (pix,d) 32x8 matvec + pool + routing stats
        #pragma unroll 1
        for (int i = 0; i < 8; i++) {
            int pairidx = tid + i*512;
            int pix = pairidx & 255;
            int d   = pairidx >> 8;
            u64 vd[8];
            #pragma unroll
            for (int ci = 0; ci < 8; ci++) {
                float v = s_votes[pix*V_ST + ci*16 + d];
                vd[ci] = pack2(v, v);
            }
            float vmax = -3.0e38f, vsum = 0.f, num = 0.f, den = 0.f;
            #pragma unroll
            for (int c2 = 0; c2 < 8; c2++) {
                u64 a0 = s_bvp[c2*2 + 0];
                u64 a1 = s_bvp[c2*2 + 1];
                #pragma unroll
                for (int ci = 0; ci < 8; ci++) {
                    ffma2(a0, vd[ci], s_wp[(c2*8 + ci)*2 + 0]);
                    ffma2(a1, vd[ci], s_wp[(c2*8 + ci)*2 + 1]);
                }
                float2 p0 = unpack2(a0), p1 = unpack2(a1);
                float v0 = p0.x, v1 = p0.y, v2 = p1.x, v3 = p1.y;
                vmax = fmaxf(vmax, fmaxf(fmaxf(v0, v1), fmaxf(v2, v3)));
                float sum4 = (v0 + v1) + (v2 + v3);
                vsum += sum4;
                float mu = 0.25f*sum4;
                float d0 = v0-mu, d1 = v1-mu, d2 = v2-mu, d3 = v3-mu;
                float var = 0.25f*((d0*d0 + d1*d1) + (d2*d2 + d3*d3));
                float rr = rsqrtf(var);
                num += rr*mu;
                den += rr;
            }
            int gpix = tb + pix;
            g_pooled[(obase*2 + 0)*PLANE + d*NPIX + gpix] = vmax;
            g_pooled[(obase*2 + 1)*PLANE + d*NPIX + gpix] = vsum*(1.f/32.f);
            g_preroute[obase*PLANE + d*NPIX + gpix] = num/den;
        }
        __syncthreads();
    }
}

// ---------------------------------------------------------------------------
// K2: spatial gate 3x3x3 conv (2ch -> 1, pad 1) + BN partial sums (fp64)
// ---------------------------------------------------------------------------
extern "C" __global__ void __launch_bounds__(512, 1)
k2_gate(const float* __restrict__ Ws)
{
    extern __shared__ float sp[];  // [2][18][34][34]
    __shared__ float s_ws[54];
    __shared__ double s_redA[16], s_redB[16];

    const int o = blockIdx.x, b = blockIdx.y;
    const int tid = threadIdx.x;
    const int obase = b*CO + o;

    if (tid < 54) s_ws[tid] = Ws[tid];
    for (int idx = tid; idx < 2*18*1156; idx += 512) {
        int ch = idx / 20808, rem = idx % 20808;
        int dd = rem / 1156, r2 = (rem % 1156)/34, cc = rem % 34;
        float v = 0.f;
        if (dd >= 1 && dd <= 16 && r2 >= 1 && r2 <= 32 && cc >= 1 && cc <= 32)
            v = g_pooled[(obase*2 + ch)*PLANE + (dd-1)*NPIX + (r2-1)*32 + (cc-1)];
        sp[idx] = v;
    }
    __syncthreads();

    const int d = tid >> 5, u = tid & 31;
    float acc[32];
    #pragma unroll
    for (int v = 0; v < 32; v++) acc[v] = 0.f;
    #pragma unroll 1
    for (int ch = 0; ch < 2; ch++) {
        #pragma unroll
        for (int kd = 0; kd < 3; kd++) {
            #pragma unroll
            for (int kh = 0; kh < 3; kh++) {
                const float* xr = sp + ch*20808 + (d+kd)*1156 + (u+kh)*34;
                float xx[34];
                #pragma unroll
                for (int j = 0; j < 34; j++) xx[j] = xr[j];
                const float* wp = s_ws + ch*27 + kd*9 + kh*3;
                float w0 = wp[0], w1 = wp[1], w2 = wp[2];
                #pragma unroll
                for (int v = 0; v < 32; v++)
                    acc[v] += w0*xx[v] + w1*xx[v+1] + w2*xx[v+2];
            }
        }
    }
    double s = 0.0, s2 = 0.0;
    float* gout = g_gate + obase*PLANE + tid*32;
    #pragma unroll
    for (int v = 0; v < 32; v++) {
        gout[v] = acc[v];
        double dv = (double)acc[v];
        s += dv; s2 += dv*dv;
    }
    #pragma unroll
    for (int off = 16; off > 0; off >>= 1) {
        s  += __shfl_down_sync(0xffffffffu, s,  off);
        s2 += __shfl_down_sync(0xffffffffu, s2, off);
    }
    int w = tid >> 5;
    if ((tid & 31) == 0) { s_redA[w] = s; s_redB[w] = s2; }
    __syncthreads();
    if (tid < 32) {
        double a = (tid < 16) ? s_redA[tid] : 0.0;
        double bq = (tid < 16) ? s_redB[tid] : 0.0;
        #pragma unroll
        for (int off = 8; off > 0; off >>= 1) {
            a  += __shfl_down_sync(0xffffffffu, a,  off);
            bq += __shfl_down_sync(0xffffffffu, bq, off);
        }
        if (tid == 0) {
            g_part[o*NB + b] = a;
            g_part[CO*NB + o*NB + b] = bq;
        }
    }
}

// ---------------------------------------------------------------------------
extern "C" __global__ void k2b_bn(const float* __restrict__ bng,
                                  const float* __restrict__ bnb)
{
    int o = threadIdx.x;
    if (o < CO) {
        double s = 0.0, s2 = 0.0;
        for (int b = 0; b < NB; b++) {
            s  += g_part[o*NB + b];
            s2 += g_part[CO*NB + o*NB + b];
        }
        double n = (double)NB * PLANE;
        double mu = s / n;
        double var = s2 / n - mu*mu;
        float rstd = (float)(1.0 / sqrt(var + 1e-5));
        float a = bng[0] * rstd;
        g_bnab[o] = a;
        g_bnab[CO + o] = bnb[0] - (float)mu * a;
    }
}

// ---------------------------------------------------------------------------
// K3: caps_next = (1+sigmoid(BN(g)))*preroute, LayerNorm, transpose-write
// ---------------------------------------------------------------------------
extern "C" __global__ void __launch_bounds__(512)
k3_finalize(const float* __restrict__ lng, const float* __restrict__ lnb,
            float* __restrict__ out)
{
    __shared__ float s_red[16];
    const int o = blockIdx.x, b = blockIdx.y;
    const int tid = threadIdx.x;
    const int base = (b*CO + o)*PLANE;
    const float a = g_bnab[o], ofs = g_bnab[CO + o];

    float x[32];
    float s = 0.f;
    #pragma unroll
    for (int i = 0; i < 32; i++) {
        int idx = tid + i*512;
        float g = g_gate[base + idx];
        float z = g*a + ofs;
        float sg = 1.f / (1.f + expf(-z));
        float val = g_preroute[base + idx] * (1.f + sg);
        x[i] = val; s += val;
    }
    #pragma unroll
    for (int off = 16; off > 0; off >>= 1) s += __shfl_down_sync(0xffffffffu, s, off);
    int w = tid >> 5;
    if ((tid & 31) == 0) s_red[w] = s;
    __syncthreads();
    if (tid < 32) {
        float t = (tid < 16) ? s_red[tid] : 0.f;
        #pragma unroll
        for (int off = 8; off > 0; off >>= 1) t += __shfl_down_sync(0xffffffffu, t, off);
        if (tid == 0) s_red[0] = t;
    }
    __syncthreads();
    float m = s_red[0] * (1.f/16384.f);
    __syncthreads();

    float v = 0.f;
    #pragma unroll
    for (int i = 0; i < 32; i++) { float dd = x[i] - m; v += dd*dd; }
    #pragma unroll
    for (int off = 16; off > 0; off >>= 1) v += __shfl_down_sync(0xffffffffu, v, off);
    if ((tid & 31) == 0) s_red[w] = v;
    __syncthreads();
    if (tid < 32) {
        float t = (tid < 16) ? s_red[tid] : 0.f;
        #pragma unroll
        for (int off = 8; off > 0; off >>= 1) t += __shfl_down_sync(0xffffffffu, t, off);
        if (tid == 0) s_red[0] = t;
    }
    __syncthreads();
    float rstd = rsqrtf(s_red[0]*(1.f/16384.f) + 1e-5f);

    float* op = out + (o*NB + b)*PLANE;
    #pragma unroll
    for (int i = 0; i < 32; i++) {
        int idx = tid + i*512;
        op[idx] = (x[i] - m)*rstd*lng[idx] + lnb[idx];
    }
}

// ---------------------------------------------------------------------------
extern "C" void kernel_launch(void* const* d_in, const int* in_sizes, int n_in,
                              void* d_out, int out_size)
{
    const float* caps = (const float*)d_in[0];
    const float* Wt   = (const float*)d_in[1];
    const float* bt   = (const float*)d_in[2];
    const float* Wv   = (const float*)d_in[3];
    const float* bv   = (const float*)d_in[4];
    const float* Ws   = (const float*)d_in[5];
    const float* bng  = (const float*)d_in[6];
    const float* bnb  = (const float*)d_in[7];
    const float* lng  = (const float*)d_in[8];
    const float* lnb  = (const float*)d_in[9];
    float* out = (float*)d_out;

    const int smem0 = DI*34*34 * 4;      // 73984
    const int smem1 = 33536 * 4;         // 134144
    const int smem2 = (2*18*1156) * 4;   // 166464
    cudaFuncSetAttribute(k0_prep,       cudaFuncAttributeMaxDynamicSharedMemorySize, smem0);
    cudaFuncSetAttribute(k1_conv_route, cudaFuncAttributeMaxDynamicSharedMemorySize, smem1);
    cudaFuncSetAttribute(k2_gate,       cudaFuncAttributeMaxDynamicSharedMemorySize, smem2);

    dim3 grid(CO, NB);
    k0_prep<<<NB + 1, 1024, smem0>>>(caps, Wt);
    k1_conv_route<<<grid, 512, smem1>>>(bt, Wv, bv);
    k2_gate<<<grid, 512, smem2>>>(Ws);
    k2b_bn<<<1, 32>>>(bng, bnb);
    k3_finalize<<<grid, 512>>>(lng, lnb, out);
}

// round 7
// speedup vs baseline: 1.3605x; 1.2212x over previous
#include <cuda_runtime.h>
#include <cuda_bf16.h>
#include <math.h>

#define NB 32
#define CI 8
#define CO 8
#define KR 4
#define DI 16
#define DOUT 16
#define SS 32
#define NPIX 1024
#define PLANE (DOUT*NPIX)   // 16384

#define KTOT 432            // 3 segments x 144 (bf16)
#define KSEG 144            // K per staged chunk (9 k16-steps)
#define AB_ST 152           // smem row stride in bf16 (76 words = 12 mod 32 -> conflict-free)
#define V_ST 129

typedef unsigned long long u64;
typedef unsigned int u32;

// ---------------- scratch (static device globals; no allocation) -------------
__device__ float g_pooled[NB*CO*2*PLANE];    // 33.5 MB
__device__ float g_preroute[NB*CO*PLANE];    // 16.8 MB
__device__ float g_gate[NB*CO*PLANE];        // 16.8 MB
__device__ double g_part[2*CO*NB];
__device__ float g_bnab[2*CO];
__device__ __nv_bfloat16 g_X2[NB*NPIX*KTOT]; // [b][pix][Xh|Xh|Xl]  28.3 MB
__device__ __nv_bfloat16 g_W2[CO*128*KTOT];  // [o][m][Wh|Wl|Wh]

// ---------------- helpers ----------------------------------------------------
__device__ __forceinline__ void ffma2(u64& d, const u64 a, const u64 b) {
    asm("fma.rn.f32x2 %0, %1, %2, %0;" : "+l"(d) : "l"(a), "l"(b));
}
__device__ __forceinline__ u64 pack2(float x, float y) {
    u64 r; asm("mov.b64 %0, {%1,%2};" : "=l"(r) : "f"(x), "f"(y)); return r;
}
__device__ __forceinline__ float2 unpack2(u64 v) {
    float2 r; asm("mov.b64 {%0,%1}, %2;" : "=f"(r.x), "=f"(r.y) : "l"(v)); return r;
}
// warp-level bf16 tensor-core mma (sm_80+ PTX, valid at compute_103 target)
__device__ __forceinline__ void mma_bf16(float* d, const u32* a, const u32* b) {
    asm volatile(
        "mma.sync.aligned.m16n8k16.row.col.f32.bf16.bf16.f32 "
        "{%0,%1,%2,%3}, {%4,%5,%6,%7}, {%8,%9}, {%0,%1,%2,%3};"
        : "+f"(d[0]), "+f"(d[1]), "+f"(d[2]), "+f"(d[3])
        : "r"(a[0]), "r"(a[1]), "r"(a[2]), "r"(a[3]), "r"(b[0]), "r"(b[1]));
}

// ---------------------------------------------------------------------------
// K0: build bf16 split operands.  blocks 0..31: X for batch b; block 32: W.
// hi = bf16(v), lo = bf16(v - hi);  X rows: [Xh|Xh|Xl], W rows: [Wh|Wl|Wh]
// ---------------------------------------------------------------------------
extern "C" __global__ void __launch_bounds__(1024)
k0_prep(const float* __restrict__ caps, const float* __restrict__ Wt)
{
    extern __shared__ float sp[];   // 16*34*34 = 18496
    const int tid = threadIdx.x;
    if (blockIdx.x < NB) {
        const int b = blockIdx.x;
        for (int idx = tid; idx < DI*1156; idx += 1024) {
            int ch = idx / 1156, rem = idx % 1156;
            int pr = rem / 34, pc = rem % 34;
            float v = 0.f;
            if (pr >= 1 && pr <= SS && pc >= 1 && pc <= SS)
                v = caps[((b*DI + ch)*SS + (pr-1))*SS + (pc-1)];
            sp[idx] = v;
        }
        __syncthreads();
        for (int idx = tid; idx < NPIX*144; idx += 1024) {
            int pix = idx / 144, s = idx % 144;
            int cin = s / 9, tap = s % 9;
            int dy = tap / 3, dx = tap % 3;
            int prow = pix >> 5, pcol = pix & 31;
            float v = sp[cin*1156 + (prow+dy)*34 + (pcol+dx)];
            __nv_bfloat16 h = __float2bfloat16(v);
            __nv_bfloat16 l = __float2bfloat16(v - __bfloat162float(h));
            __nv_bfloat16* dst = g_X2 + (pix + (u64)b*NPIX)*KTOT + s;
            dst[0]   = h;      // seg0: Xh
            dst[144] = h;      // seg1: Xh
            dst[288] = l;      // seg2: Xl
        }
    } else {
        for (int idx = tid; idx < CO*128*144; idx += 1024) {
            int s = idx % 144, m = (idx/144) & 127, o = idx/(144*128);
            int c = m >> 4, d = m & 15;
            float v = Wt[(((c*CO + o)*DOUT + d)*144) + s];
            __nv_bfloat16 h = __float2bfloat16(v);
            __nv_bfloat16 l = __float2bfloat16(v - __bfloat162float(h));
            __nv_bfloat16* dst = g_W2 + (o*128 + m)*KTOT + s;
            dst[0]   = h;      // seg0: Wh
            dst[144] = l;      // seg1: Wl
            dst[288] = h;      // seg2: Wh
        }
    }
}

// ---------------------------------------------------------------------------
// K1: mma.sync bf16 3-split conv-GEMM (M=128, N=1024, K=432) + einsum + pool
// + routing-pre.  grid (o=8, b=32), 512 threads, 134 KB dynamic smem.
// smem bytes: [0,2048) tables | [2048,40960) s_A 128x152 bf16
//   [40960,118784) s_B 256x152 bf16 | votes aliases [2048,134144) 256x129 f32
// ---------------------------------------------------------------------------
extern "C" __global__ void __launch_bounds__(512, 1)
k1_conv_route(const float* __restrict__ bt, const float* __restrict__ Wv,
              const float* __restrict__ bv)
{
    extern __shared__ float sm[];
    u64*   s_wp    = (u64*)sm;                       // 128 u64
    u64*   s_bvp   = (u64*)(sm + 256);               // 16 u64
    float* s_bias  = sm + 288;                       // 128
    __nv_bfloat16* s_A = (__nv_bfloat16*)(sm + 512); // 128 x AB_ST
    __nv_bfloat16* s_B = s_A + 128*AB_ST;            // 256 x AB_ST
    float* s_votes = sm + 512;                       // aliases A/B

    const int o = blockIdx.x, b = blockIdx.y;
    const int tid  = threadIdx.x;
    const int w    = tid >> 5, lane = tid & 31;
    const int wm   = w & 3,  wn = w >> 2;       // warp tile rows wm*32, cols wn*64
    const int g    = lane >> 2, t = lane & 3;
    const int obase = b*CO + o;

    // tables
    for (int idx = tid; idx < 128; idx += 512) {
        int c2 = idx >> 4, ci = (idx >> 1) & 7, h = idx & 1;
        s_wp[idx] = pack2(Wv[o*256 + ((2*h)*8 + c2)*8 + ci],
                          Wv[o*256 + ((2*h+1)*8 + c2)*8 + ci]);
    }
    if (tid < 16) {
        int c2 = tid >> 1, h = tid & 1;
        s_bvp[tid] = pack2(bv[o*32 + (2*h)*8 + c2], bv[o*32 + (2*h+1)*8 + c2]);
    }
    if (tid < 128)
        s_bias[tid] = bt[(((tid >> 4)*CO + o)*DOUT) + (tid & 15)];
    __syncthreads();

    for (int ntile = 0; ntile < 4; ntile++) {
        const int tb = ntile*256;
        float acc[2][8][4];
        #pragma unroll
        for (int mi = 0; mi < 2; mi++)
            #pragma unroll
            for (int nj = 0; nj < 8; nj++)
                #pragma unroll
                for (int e = 0; e < 4; e++) acc[mi][nj][e] = 0.f;

        for (int seg = 0; seg < 3; seg++) {
            const int koff = seg*KSEG;   // bf16 units
            // stage A: 128 rows x 18 float4 (144 bf16/row)
            #pragma unroll
            for (int i = tid; i < 2304; i += 512) {
                int m = i / 18, j = i % 18;
                float4 v = ((const float4*)(g_W2 + (o*128 + m)*KTOT + koff))[j];
                ((float4*)((char*)s_A + m*(AB_ST*2)))[j] = v;
            }
            // stage B: 256 rows x 18 float4
            #pragma unroll
            for (int i = tid; i < 4608; i += 512) {
                int pr = i / 18, j = i % 18;
                float4 v = ((const float4*)(g_X2 + ((u64)b*NPIX + tb + pr)*KTOT + koff))[j];
                ((float4*)((char*)s_B + pr*(AB_ST*2)))[j] = v;
            }
            __syncthreads();
            // 9 k16-steps
            #pragma unroll
            for (int ks = 0; ks < 9; ks++) {
                const int kb = ks*16;    // bf16 units
                u32 afr[2][4];
                #pragma unroll
                for (int mi = 0; mi < 2; mi++) {
                    const __nv_bfloat16* ar = s_A + (wm*32 + mi*16 + g)*AB_ST + kb + 2*t;
                    afr[mi][0] = *(const u32*)(ar);
                    afr[mi][1] = *(const u32*)(ar + 8*AB_ST);
                    afr[mi][2] = *(const u32*)(ar + 8);
                    afr[mi][3] = *(const u32*)(ar + 8*AB_ST + 8);
                }
                u32 bfr[8][2];
                #pragma unroll
                for (int nj = 0; nj < 8; nj++) {
                    const __nv_bfloat16* br = s_B + (wn*64 + nj*8 + g)*AB_ST + kb + 2*t;
                    bfr[nj][0] = *(const u32*)(br);
                    bfr[nj][1] = *(const u32*)(br + 8);
                }
                #pragma unroll
                for (int mi = 0; mi < 2; mi++)
                    #pragma unroll
                    for (int nj = 0; nj < 8; nj++)
                        mma_bf16(acc[mi][nj], afr[mi], bfr[nj]);
            }
            __syncthreads();
        }

        // ---- stage votes (+bias) into s_votes[pix][m] (aliases A/B; accs in regs)
        #pragma unroll
        for (int mi = 0; mi < 2; mi++) {
            int m0 = wm*32 + mi*16 + g;
            float bias0 = s_bias[m0], bias1 = s_bias[m0 + 8];
            #pragma unroll
            for (int nj = 0; nj < 8; nj++) {
                int p0 = wn*64 + nj*8 + 2*t;
                s_votes[p0*V_ST + m0]           = acc[mi][nj][0] + bias0;
                s_votes[(p0+1)*V_ST + m0]       = acc[mi][nj][1] + bias0;
                s_votes[p0*V_ST + m0 + 8]       = acc[mi][nj][2] + bias1;
                s_votes[(p0+1)*V_ST + m0 + 8]   = acc[mi][nj][3] + bias1;
            }
        }
        __syncthreads();

        // ---- Phase B: per (pix,d) 32x8 matvec + pool + routing stats
        #pragma unroll 1
        for (int i = 0; i < 8; i++) {
            int pairidx = tid + i*512;
            int pix = pairidx & 255;
            int d   = pairidx >> 8;
            u64 vd[8];
            #pragma unroll
            for (int ci = 0; ci < 8; ci++) {
                float v = s_votes[pix*V_ST + ci*16 + d];
                vd[ci] = pack2(v, v);
            }
            float vmax = -3.0e38f, vsum = 0.f, num = 0.f, den = 0.f;
            #pragma unroll
            for (int c2 = 0; c2 < 8; c2++) {
                u64 a0 = s_bvp[c2*2 + 0];
                u64 a1 = s_bvp[c2*2 + 1];
                #pragma unroll
                for (int ci = 0; ci < 8; ci++) {
                    ffma2(a0, vd[ci], s_wp[(c2*8 + ci)*2 + 0]);
                    ffma2(a1, vd[ci], s_wp[(c2*8 + ci)*2 + 1]);
                }
                float2 p0 = unpack2(a0), p1 = unpack2(a1);
                float v0 = p0.x, v1 = p0.y, v2 = p1.x, v3 = p1.y;
                vmax = fmaxf(vmax, fmaxf(fmaxf(v0, v1), fmaxf(v2, v3)));
                float sum4 = (v0 + v1) + (v2 + v3);
                vsum += sum4;
                float mu = 0.25f*sum4;
                float d0 = v0-mu, d1 = v1-mu, d2 = v2-mu, d3 = v3-mu;
                float var = 0.25f*((d0*d0 + d1*d1) + (d2*d2 + d3*d3));
                float rr = rsqrtf(var);
                num += rr*mu;
                den += rr;
            }
            int gpix = tb + pix;
            g_pooled[(obase*2 + 0)*PLANE + d*NPIX + gpix] = vmax;
            g_pooled[(obase*2 + 1)*PLANE + d*NPIX + gpix] = vsum*(1.f/32.f);
            g_preroute[obase*PLANE + d*NPIX + gpix] = num/den;
        }
        __syncthreads();
    }
}

// ---------------------------------------------------------------------------
// K2: spatial gate 3x3x3 conv (2ch -> 1, pad 1) + BN partial sums (fp64)
// ---------------------------------------------------------------------------
extern "C" __global__ void __launch_bounds__(512, 1)
k2_gate(const float* __restrict__ Ws)
{
    extern __shared__ float sp[];  // [2][18][34][34]
    __shared__ float s_ws[54];
    __shared__ double s_redA[16], s_redB[16];

    const int o = blockIdx.x, b = blockIdx.y;
    const int tid = threadIdx.x;
    const int obase = b*CO + o;

    if (tid < 54) s_ws[tid] = Ws[tid];
    for (int idx = tid; idx < 2*18*1156; idx += 512) {
        int ch = idx / 20808, rem = idx % 20808;
        int dd = rem / 1156, r2 = (rem % 1156)/34, cc = rem % 34;
        float v = 0.f;
        if (dd >= 1 && dd <= 16 && r2 >= 1 && r2 <= 32 && cc >= 1 && cc <= 32)
            v = g_pooled[(obase*2 + ch)*PLANE + (dd-1)*NPIX + (r2-1)*32 + (cc-1)];
        sp[idx] = v;
    }
    __syncthreads();

    const int d = tid >> 5, u = tid & 31;
    float acc[32];
    #pragma unroll
    for (int v = 0; v < 32; v++) acc[v] = 0.f;
    #pragma unroll 1
    for (int ch = 0; ch < 2; ch++) {
        #pragma unroll
        for (int kd = 0; kd < 3; kd++) {
            #pragma unroll
            for (int kh = 0; kh < 3; kh++) {
                const float* xr = sp + ch*20808 + (d+kd)*1156 + (u+kh)*34;
                float xx[34];
                #pragma unroll
                for (int j = 0; j < 34; j++) xx[j] = xr[j];
                const float* wp = s_ws + ch*27 + kd*9 + kh*3;
                float w0 = wp[0], w1 = wp[1], w2 = wp[2];
                #pragma unroll
                for (int v = 0; v < 32; v++)
                    acc[v] += w0*xx[v] + w1*xx[v+1] + w2*xx[v+2];
            }
        }
    }
    double s = 0.0, s2 = 0.0;
    float* gout = g_gate + obase*PLANE + tid*32;
    #pragma unroll
    for (int v = 0; v < 32; v++) {
        gout[v] = acc[v];
        double dv = (double)acc[v];
        s += dv; s2 += dv*dv;
    }
    #pragma unroll
    for (int off = 16; off > 0; off >>= 1) {
        s  += __shfl_down_sync(0xffffffffu, s,  off);
        s2 += __shfl_down_sync(0xffffffffu, s2, off);
    }
    int w = tid >> 5;
    if ((tid & 31) == 0) { s_redA[w] = s; s_redB[w] = s2; }
    __syncthreads();
    if (tid < 32) {
        double a = (tid < 16) ? s_redA[tid] : 0.0;
        double bq = (tid < 16) ? s_redB[tid] : 0.0;
        #pragma unroll
        for (int off = 8; off > 0; off >>= 1) {
            a  += __shfl_down_sync(0xffffffffu, a,  off);
            bq += __shfl_down_sync(0xffffffffu, bq, off);
        }
        if (tid == 0) {
            g_part[o*NB + b] = a;
            g_part[CO*NB + o*NB + b] = bq;
        }
    }
}

// ---------------------------------------------------------------------------
extern "C" __global__ void k2b_bn(const float* __restrict__ bng,
                                  const float* __restrict__ bnb)
{
    int o = threadIdx.x;
    if (o < CO) {
        double s = 0.0, s2 = 0.0;
        for (int b = 0; b < NB; b++) {
            s  += g_part[o*NB + b];
            s2 += g_part[CO*NB + o*NB + b];
        }
        double n = (double)NB * PLANE;
        double mu = s / n;
        double var = s2 / n - mu*mu;
        float rstd = (float)(1.0 / sqrt(var + 1e-5));
        float a = bng[0] * rstd;
        g_bnab[o] = a;
        g_bnab[CO + o] = bnb[0] - (float)mu * a;
    }
}

// ---------------------------------------------------------------------------
// K3: caps_next = (1+sigmoid(BN(g)))*preroute, LayerNorm, transpose-write
// ---------------------------------------------------------------------------
extern "C" __global__ void __launch_bounds__(512)
k3_finalize(const float* __restrict__ lng, const float* __restrict__ lnb,
            float* __restrict__ out)
{
    __shared__ float s_red[16];
    const int o = blockIdx.x, b = blockIdx.y;
    const int tid = threadIdx.x;
    const int base = (b*CO + o)*PLANE;
    const float a = g_bnab[o], ofs = g_bnab[CO + o];

    float x[32];
    float s = 0.f;
    #pragma unroll
    for (int i = 0; i < 32; i++) {
        int idx = tid + i*512;
        float g = g_gate[base + idx];
        float z = g*a + ofs;
        float sg = 1.f / (1.f + expf(-z));
        float val = g_preroute[base + idx] * (1.f + sg);
        x[i] = val; s += val;
    }
    #pragma unroll
    for (int off = 16; off > 0; off >>= 1) s += __shfl_down_sync(0xffffffffu, s, off);
    int w = tid >> 5;
    if ((tid & 31) == 0) s_red[w] = s;
    __syncthreads();
    if (tid < 32) {
        float t = (tid < 16) ? s_red[tid] : 0.f;
        #pragma unroll
        for (int off = 8; off > 0; off >>= 1) t += __shfl_down_sync(0xffffffffu, t, off);
        if (tid == 0) s_red[0] = t;
    }
    __syncthreads();
    float m = s_red[0] * (1.f/16384.f);
    __syncthreads();

    float v = 0.f;
    #pragma unroll
    for (int i = 0; i < 32; i++) { float dd = x[i] - m; v += dd*dd; }
    #pragma unroll
    for (int off = 16; off > 0; off >>= 1) v += __shfl_down_sync(0xffffffffu, v, off);
    if ((tid & 31) == 0) s_red[w] = v;
    __syncthreads();
    if (tid < 32) {
        float t = (tid < 16) ? s_red[tid] : 0.f;
        #pragma unroll
        for (int off = 8; off > 0; off >>= 1) t += __shfl_down_sync(0xffffffffu, t, off);
        if (tid == 0) s_red[0] = t;
    }
    __syncthreads();
    float rstd = rsqrtf(s_red[0]*(1.f/16384.f) + 1e-5f);

    float* op = out + (o*NB + b)*PLANE;
    #pragma unroll
    for (int i = 0; i < 32; i++) {
        int idx = tid + i*512;
        op[idx] = (x[i] - m)*rstd*lng[idx] + lnb[idx];
    }
}

// ---------------------------------------------------------------------------
extern "C" void kernel_launch(void* const* d_in, const int* in_sizes, int n_in,
                              void* d_out, int out_size)
{
    const float* caps = (const float*)d_in[0];
    const float* Wt   = (const float*)d_in[1];
    const float* bt   = (const float*)d_in[2];
    const float* Wv   = (const float*)d_in[3];
    const float* bv   = (const float*)d_in[4];
    const float* Ws   = (const float*)d_in[5];
    const float* bng  = (const float*)d_in[6];
    const float* bnb  = (const float*)d_in[7];
    const float* lng  = (const float*)d_in[8];
    const float* lnb  = (const float*)d_in[9];
    float* out = (float*)d_out;

    const int smem0 = DI*34*34 * 4;      // 73984
    const int smem1 = 134144;            // tables + max(A+B, votes)
    const int smem2 = (2*18*1156) * 4;   // 166464
    cudaFuncSetAttribute(k0_prep,       cudaFuncAttributeMaxDynamicSharedMemorySize, smem0);
    cudaFuncSetAttribute(k1_conv_route, cudaFuncAttributeMaxDynamicSharedMemorySize, smem1);
    cudaFuncSetAttribute(k2_gate,       cudaFuncAttributeMaxDynamicSharedMemorySize, smem2);

    dim3 grid(CO, NB);
    k0_prep<<<NB + 1, 1024, smem0>>>(caps, Wt);
    k1_conv_route<<<grid, 512, smem1>>>(bt, Wv, bv);
    k2_gate<<<grid, 512, smem2>>>(Ws);
    k2b_bn<<<1, 32>>>(bng, bnb);
    k3_finalize<<<grid, 512>>>(lng, lnb, out);
}